// round 16
// baseline (speedup 1.0000x reference)
#include <cuda_runtime.h>
#include <cuda_fp16.h>
#include <cstdint>

#define BB 32
#define SS 128
#define UU 256
#define HH 128
#define VV 30001
#define NU 938               // 32-col n-units (938*32 = 30016 >= 30001)
#define NT_M 32              // m tiles of 128
#define GRID_G 148

__device__ __half g_outs[BB * SS * HH];   // RNN outputs, TIME-MAJOR: row = t*32 + b
__device__ int    g_step_done[SS];        // per-step completion counters (0..32)
__device__ int    g_gemm_done;            // gemm CTA completion counter

// ---------------------------------------------------------------------------
__device__ __forceinline__ uint32_t smem_u32(const void* p) {
    uint32_t a;
    asm("{ .reg .u64 t; cvta.to.shared.u64 t, %1; cvt.u32.u64 %0, t; }" : "=r"(a) : "l"(p));
    return a;
}
#define CP_ASYNC16(s, g) \
    asm volatile("cp.async.cg.shared.global [%0], [%1], 16;" :: "r"(s), "l"(g) : "memory")
#define CP_COMMIT()  asm volatile("cp.async.commit_group;" ::: "memory")
#define CP_WAIT0()   asm volatile("cp.async.wait_group 0;" ::: "memory")

#define LDS128U(r0, r1, r2, r3, addr) \
    asm volatile("ld.shared.v4.u32 {%0,%1,%2,%3}, [%4];" \
                 : "=r"(r0), "=r"(r1), "=r"(r2), "=r"(r3) : "r"(addr))

__device__ __forceinline__ void mma_f16(float* d, const uint32_t* a, uint32_t b0, uint32_t b1) {
    asm volatile("mma.sync.aligned.m16n8k16.row.col.f32.f16.f16.f32 "
                 "{%0,%1,%2,%3}, {%4,%5,%6,%7}, {%8,%9}, {%0,%1,%2,%3};"
                 : "+f"(d[0]), "+f"(d[1]), "+f"(d[2]), "+f"(d[3])
                 : "r"(a[0]), "r"(a[1]), "r"(a[2]), "r"(a[3]), "r"(b0), "r"(b1));
}

// ---------------------------------------------------------------------------
// RNN: one CTA per batch, 384 threads. User state SLOT-COMPRESSED (first-touch,
// <=128 slots, init from h0) so smem ~69.6KB and a gemm CTA always co-resides.
// Writes g_outs TIME-MAJOR and publishes per-step progress flags.
// ---------------------------------------------------------------------------
#define RNN_SMEM 69632

__global__ __launch_bounds__(384, 1)
void rnn_kernel(const int* __restrict__ users, const int* __restrict__ items,
                const float* __restrict__ h0,
                const float* __restrict__ P_ru, const float* __restrict__ W_ru,
                const float* __restrict__ b_ru,
                const float* __restrict__ P_c, const float* __restrict__ W_c,
                const float* __restrict__ b_c)
{
    extern __shared__ float sm[];
    float* state_s = sm;                    // 128 slots x 128
    float* rh_s    = sm + 16384;            // 128
    float* z_s     = rh_s + 128;            // 128
    int*   items_s = (int*)(z_s + 128);     // 128
    int*   useq    = items_s + SS;          // 128 (slot ids)
    int*   u2slot  = useq + SS;             // 256
    int*   slotu   = u2slot + UU;           // 128
    int*   nslots_p = slotu + SS;           // 1

    const int b   = blockIdx.x;
    const int tid = threadIdx.x;

    for (int t = tid; t < SS; t += 384) {
        items_s[t] = items[b * SS + t];
        useq[t]    = users[b * SS + t];     // raw user ids for now
    }
    for (int i = tid; i < UU; i += 384) u2slot[i] = -1;
    __syncthreads();
    if (tid == 0) {
        int ns = 0;
        for (int t = 0; t < SS; t++) {
            int u = useq[t];
            int s = u2slot[u];
            if (s < 0) { s = ns++; u2slot[u] = s; slotu[s] = u; }
            useq[t] = s;                    // now slot ids
        }
        *nslots_p = ns;
    }
    __syncthreads();
    const int ns = *nslots_p;
    for (int idx = tid; idx < ns * HH; idx += 384) {
        int s = idx >> 7, j = idx & 127;
        state_s[idx] = h0[((size_t)b * UU + slotu[s]) * HH + j];
    }

    float wreg[HH];
    float breg;
    if (tid < 2 * HH) {
        #pragma unroll
        for (int k = 0; k < HH; k++) wreg[k] = W_ru[k * (2 * HH) + tid];
        breg = b_ru[tid];
    } else {
        const int j = tid - 2 * HH;
        #pragma unroll
        for (int k = 0; k < HH; k++) wreg[k] = W_c[k * HH + j];
        breg = b_c[j];
    }
    __syncthreads();

    float pA;
    {
        int it0 = items_s[0];
        pA = (tid < 2 * HH) ? P_ru[(size_t)it0 * (2 * HH) + tid]
                            : P_c[(size_t)it0 * HH + (tid - 2 * HH)];
    }

    for (int t = 0; t < SS; t++) {
        const int u = useq[t];              // slot id
        const int itn = items_s[(t + 1) & (SS - 1)];
        float pN = (tid < 2 * HH) ? P_ru[(size_t)itn * (2 * HH) + tid]
                                  : P_c[(size_t)itn * HH + (tid - 2 * HH)];

        if (tid < 2 * HH) {
            const float* hs = state_s + u * HH;
            float a0 = 0.f, a1 = 0.f, a2 = 0.f, a3 = 0.f;
            float a4 = 0.f, a5 = 0.f, a6 = 0.f, a7 = 0.f;
            #pragma unroll
            for (int k = 0; k < HH; k += 8) {
                float4 h4 = *(const float4*)(hs + k);
                float4 h5 = *(const float4*)(hs + k + 4);
                a0 += h4.x * wreg[k];     a1 += h4.y * wreg[k + 1];
                a2 += h4.z * wreg[k + 2]; a3 += h4.w * wreg[k + 3];
                a4 += h5.x * wreg[k + 4]; a5 += h5.y * wreg[k + 5];
                a6 += h5.z * wreg[k + 6]; a7 += h5.w * wreg[k + 7];
            }
            float x = pA + breg + ((a0 + a1) + (a2 + a3)) + ((a4 + a5) + (a6 + a7));
            float sgm = 1.f / (1.f + __expf(-x));
            if (tid < HH) rh_s[tid] = sgm * hs[tid];
            else          z_s[tid - HH] = sgm;
        }
        __syncthreads();

        if (tid >= 2 * HH) {
            const int j = tid - 2 * HH;
            float a0 = 0.f, a1 = 0.f, a2 = 0.f, a3 = 0.f;
            float a4 = 0.f, a5 = 0.f, a6 = 0.f, a7 = 0.f;
            #pragma unroll
            for (int k = 0; k < HH; k += 8) {
                float4 r4 = *(const float4*)(rh_s + k);
                float4 r5 = *(const float4*)(rh_s + k + 4);
                a0 += r4.x * wreg[k];     a1 += r4.y * wreg[k + 1];
                a2 += r4.z * wreg[k + 2]; a3 += r4.w * wreg[k + 3];
                a4 += r5.x * wreg[k + 4]; a5 += r5.y * wreg[k + 5];
                a6 += r5.z * wreg[k + 6]; a7 += r5.w * wreg[k + 7];
            }
            float x = pA + breg + ((a0 + a1) + (a2 + a3)) + ((a4 + a5) + (a6 + a7));
            float c = tanhf(x);
            float h_old = state_s[u * HH + j];
            float z = z_s[j];
            float hn = z * h_old + (1.f - z) * c;
            state_s[u * HH + j] = hn;
            g_outs[((size_t)(t * 32 + b)) * HH + j] = __float2half(hn);  // time-major
            __threadfence();                 // writer fence before flag
        }
        __syncthreads();
        if (tid == 0) atomicAdd(&g_step_done[t], 1);
        pA = pN;
    }
}

// ---------------------------------------------------------------------------
// Persistent GEMM (fp16 in, f32 acc), overlapped with the RNN via flags.
// 148 CTAs (1/SM guaranteed) x 256 threads. Each CTA: 6-7 32-col n-units,
// B images built in-prologue from ws (no prep kernel), resident in smem.
// Per mt: spin for RNN steps 4mt..4mt+3, A cp.async'd into padded smem,
// A(mt+1) prefetch overlapped. Epilogue: Cs transpose -> coalesced stores,
// row remap (m&31)*128 + (m>>5) restores batch-major output ordering.
// ---------------------------------------------------------------------------
#define SM_B_OFF  0          // 7 * 8192 = 57344
#define SM_A_OFF  57344      // 128 rows * 272 B = 34816
#define SM_C_OFF  92160      // 32 cols * 137 words * 4 B = 17536
#define GEMM_SMEM 109696

__device__ __forceinline__ void wait_step(int t) {
    if (threadIdx.x == 0) {
        volatile int* f = g_step_done;
        while (f[t] < BB) __nanosleep(64);
    }
    __syncthreads();
}

__device__ __forceinline__ void stage_A(uint32_t sbase, int mt, int tid) {
    const char* srcA = (const char*)g_outs + (size_t)mt * 32768;
    #pragma unroll
    for (int j = 0; j < 8; j++) {
        int ch = tid + j * 256;
        CP_ASYNC16(sbase + SM_A_OFF + (ch >> 4) * 272 + (ch & 15) * 16, srcA + ch * 16);
    }
}

__global__ __launch_bounds__(256)
void gemm_kernel(const float* __restrict__ ws, float* __restrict__ out)
{
    extern __shared__ uint32_t smu[];
    const int tid = threadIdx.x;
    const int w = tid >> 5, l = tid & 31;
    const uint32_t sbase = smem_u32(smu);
    const int c = l & 3, r = l >> 2;

    const int cta = blockIdx.x;
    // 938 units = 148*6 + 50 -> first 50 CTAs take 7
    const int ustart = cta * 6 + (cta < 50 ? cta : 50);
    const int count  = 6 + (cta < 50 ? 1 : 0);

    // ---- prologue: build B fragment images from ws (raw staged in A region) ----
    {
        float* raw = (float*)(smu + SM_A_OFF / 4);   // [128][32]
        for (int uu = 0; uu < count; uu++) {
            const int n0 = (ustart + uu) * 32;
            for (int idx = tid; idx < 4096; idx += 256) {
                int k = idx >> 5, n = idx & 31;
                int gn = n0 + n;
                raw[idx] = (gn < VV) ? ws[(size_t)k * VV + gn] : 0.f;
            }
            __syncthreads();
            uint32_t* dst = smu + (SM_B_OFF / 4) + uu * 2048;
            for (int Wd = tid; Wd < 2048; Wd += 256) {
                int w4  = Wd & 3;
                int ll  = (Wd >> 2) & 31;
                int blk = Wd >> 7;                   // nf*4 + ksp, nf 0..3
                int nf  = blk >> 2, ksp = blk & 3;
                int n   = nf * 8 + (ll >> 2);
                int kb  = 32 * ksp + 2 * (ll & 3) + 8 * w4;
                __half2 h = __floats2half2_rn(raw[kb * 32 + n], raw[(kb + 1) * 32 + n]);
                dst[Wd] = *(const uint32_t*)&h;
            }
            __syncthreads();
        }
    }

    const uint32_t* smA = smu + SM_A_OFF / 4;
    float* Cs = (float*)(smu + SM_C_OFF / 4);

    // first A tile
    wait_step(3);
    stage_A(sbase, 0, tid);
    CP_COMMIT();
    CP_WAIT0();
    __syncthreads();

    for (int mt = 0; mt < NT_M; mt++) {
        if (mt > 0) {            // A(mt) group issued last iteration
            CP_WAIT0();
            __syncthreads();
        }

        // A fragments from smem (conflict-free: bank = 4r + c + 8ks)
        uint32_t a[8][4];
        {
            const int w0 = (w * 16 + r) * 68 + c;
            #pragma unroll
            for (int ks = 0; ks < 8; ks++) {
                int b0 = w0 + 8 * ks;
                a[ks][0] = smA[b0];
                a[ks][1] = smA[b0 + 544];
                a[ks][2] = smA[b0 + 4];
                a[ks][3] = smA[b0 + 548];
            }
        }
        __syncthreads();         // all warps done reading A(mt)

        if (mt + 1 < NT_M) {     // wait producer, then prefetch A(mt+1)
            wait_step(4 * (mt + 1) + 3);
            stage_A(sbase, mt + 1, tid);
            CP_COMMIT();
        }

        for (int uu = 0; uu < count; uu++) {
            const int u = ustart + uu;
            float acc[4][4];
            #pragma unroll
            for (int nf = 0; nf < 4; nf++) {
                acc[nf][0] = 0.f; acc[nf][1] = 0.f; acc[nf][2] = 0.f; acc[nf][3] = 0.f;
            }

            const uint32_t Bu = sbase + SM_B_OFF + (uint32_t)uu * 8192 + (uint32_t)l * 16;
            #pragma unroll
            for (int ksp = 0; ksp < 4; ksp++) {
                uint32_t bf[4][4];
                #pragma unroll
                for (int nf = 0; nf < 4; nf++)
                    LDS128U(bf[nf][0], bf[nf][1], bf[nf][2], bf[nf][3],
                            Bu + (uint32_t)((nf * 4 + ksp) * 512));
                #pragma unroll
                for (int nf = 0; nf < 4; nf++)
                    mma_f16(acc[nf], a[2 * ksp], bf[nf][0], bf[nf][1]);
                #pragma unroll
                for (int nf = 0; nf < 4; nf++)
                    mma_f16(acc[nf], a[2 * ksp + 1], bf[nf][2], bf[nf][3]);
            }

            // epilogue: acc -> Cs (column-major, stride 137) -> coalesced stores
            {
                const int row0 = w * 16 + r;
                #pragma unroll
                for (int nf = 0; nf < 4; nf++) {
                    int c0 = (c * 2 + nf * 8) * 137;
                    Cs[c0 + row0]           = acc[nf][0];
                    Cs[c0 + 137 + row0]     = acc[nf][1];
                    Cs[c0 + row0 + 8]       = acc[nf][2];
                    Cs[c0 + 137 + row0 + 8] = acc[nf][3];
                }
            }
            __syncthreads();
            {
                const int gcol = u * 32 + l;
                if (u != NU - 1 || gcol < VV) {
                    #pragma unroll
                    for (int i = 0; i < 16; i++) {
                        int row = 8 * i + w;
                        int m = mt * 128 + row;                 // time-major index
                        size_t orow = (size_t)((m & 31) * 128 + (m >> 5));  // b*128 + t
                        out[orow * VV + gcol] = Cs[l * 137 + row];
                    }
                }
            }
            __syncthreads();
        }
    }

    // flag reset for next graph replay (last CTA only)
    __syncthreads();
    if (tid == 0) {
        int v = atomicAdd(&g_gemm_done, 1);
        if (v == GRID_G - 1) {
            for (int i = 0; i < SS; i++) g_step_done[i] = 0;
            g_gemm_done = 0;
            __threadfence();
        }
    }
}

// ---------------------------------------------------------------------------
extern "C" void kernel_launch(void* const* d_in, const int* in_sizes, int n_in,
                              void* d_out, int out_size)
{
    const int*   users = (const int*)d_in[0];
    const int*   items = (const int*)d_in[1];
    const float* h0    = (const float*)d_in[2];
    const float* P_ru  = (const float*)d_in[3];
    const float* W_ru  = (const float*)d_in[4];
    const float* b_ru  = (const float*)d_in[5];
    const float* P_c   = (const float*)d_in[6];
    const float* W_c   = (const float*)d_in[7];
    const float* b_c   = (const float*)d_in[8];
    const float* ws    = (const float*)d_in[9];
    float* out = (float*)d_out;

    static cudaStream_t s2;
    static cudaEvent_t ef, ej;
    static int init_done = 0;
    if (!init_done) {
        cudaStreamCreateWithFlags(&s2, cudaStreamNonBlocking);
        cudaEventCreateWithFlags(&ef, cudaEventDisableTiming);
        cudaEventCreateWithFlags(&ej, cudaEventDisableTiming);
        cudaFuncSetAttribute(rnn_kernel,  cudaFuncAttributeMaxDynamicSharedMemorySize, RNN_SMEM);
        cudaFuncSetAttribute(gemm_kernel, cudaFuncAttributeMaxDynamicSharedMemorySize, GEMM_SMEM);
        init_done = 1;
    }

    // fork: gemm runs concurrently on s2, overlapped with the RNN via flags
    cudaEventRecord(ef, 0);
    cudaStreamWaitEvent(s2, ef, 0);

    rnn_kernel<<<BB, 384, RNN_SMEM>>>(users, items, h0, P_ru, W_ru, b_ru, P_c, W_c, b_c);
    gemm_kernel<<<GRID_G, 256, GEMM_SMEM, s2>>>(ws, out);

    // join
    cudaEventRecord(ej, s2);
    cudaStreamWaitEvent(0, ej, 0);
}